// round 7
// baseline (speedup 1.0000x reference)
#include <cuda_runtime.h>

// Round 7: de-serialize. Projections: double-buffered smem (1 barrier/k-tile,
// STS/LDG overlap compute). Attention: separate K and V buffers (70KB, still
// 2 blocks/SM on the 228KB carveout) -> 3 barriers/tile, K+V loads fused.

#define EMBED 1024
#define NHEAD 16
#define HDIM  64
#define BATCH 2
#define SEQ   2048
#define MTOT  (BATCH*SEQ)

#define PBM 128
#define PBN 128
#define PBK 16
#define PADT 132

#define PADP 68
#define ATTN_FLOATS (4*64*PADP + 128)   // Qs, Ks, Vs, Ps + corr_s + l_s
#define ATTN_SMEM   (ATTN_FLOATS*4)

typedef unsigned long long u64;

__device__ __forceinline__ u64 pk2(float a) {
    u64 r; asm("mov.b64 %0, {%1, %1};" : "=l"(r) : "f"(a)); return r;
}
__device__ __forceinline__ void fma2(u64& d, u64 a, u64 b) {
    asm("fma.rn.f32x2 %0, %1, %2, %0;" : "+l"(d) : "l"(a), "l"(b));
}
__device__ __forceinline__ void mul2(u64& d, u64 a) {
    asm("mul.rn.f32x2 %0, %0, %1;" : "+l"(d) : "l"(a));
}
__device__ __forceinline__ float2 up2(u64 v) {
    float2 r; asm("mov.b64 {%0, %1}, %2;" : "=f"(r.x), "=f"(r.y) : "l"(v)); return r;
}

__device__ float g_q[BATCH*NHEAD*SEQ*HDIM];
__device__ float g_k[BATCH*NHEAD*SEQ*HDIM];
__device__ float g_v[BATCH*NHEAD*SEQ*HDIM];
__device__ float g_h[MTOT*EMBED];

// ---------------------------------------------------------------------------
// 128x128x16 SGEMM body, double-buffered smem, 8x4 packed-f32x2 accumulators.
// One __syncthreads per k-tile.
// ---------------------------------------------------------------------------
#define PROJ_STS(S)                                                            \
    As[S][lc8+0][lr] = a0.x; As[S][lc8+1][lr] = a0.y;                          \
    As[S][lc8+2][lr] = a0.z; As[S][lc8+3][lr] = a0.w;                          \
    As[S][lc8+4][lr] = a1.x; As[S][lc8+5][lr] = a1.y;                          \
    As[S][lc8+6][lr] = a1.z; As[S][lc8+7][lr] = a1.w;                          \
    Bs[S][lc8+0][lr] = w0.x; Bs[S][lc8+1][lr] = w0.y;                          \
    Bs[S][lc8+2][lr] = w0.z; Bs[S][lc8+3][lr] = w0.w;                          \
    Bs[S][lc8+4][lr] = w1.x; Bs[S][lc8+5][lr] = w1.y;                          \
    Bs[S][lc8+6][lr] = w1.z; Bs[S][lc8+7][lr] = w1.w;

#define PROJ_BODY(APTR, WPTR)                                                  \
    __shared__ float As[2][PBK][PADT];                                         \
    __shared__ float Bs[2][PBK][PADT];                                         \
    const int tid = threadIdx.x;                                               \
    const int m0 = blockIdx.y * PBM;                                           \
    const int n0 = blockIdx.x * PBN;                                           \
    const int lr  = tid >> 1;                                                  \
    const int lc8 = (tid & 1) << 3;                                            \
    const int ty4 = (tid >> 4) << 2;                                           \
    const int tx4 = (tid & 15) << 2;                                           \
    const float* Ap = (APTR) + (size_t)(m0 + lr) * EMBED + lc8;                \
    const float* Wp = (WPTR) + (size_t)(n0 + lr) * EMBED + lc8;                \
    u64 acc2[8][4];                                                            \
    _Pragma("unroll")                                                          \
    for (int i = 0; i < 8; i++)                                                \
        _Pragma("unroll")                                                      \
        for (int j = 0; j < 4; j++) acc2[i][j] = 0ull;                         \
    float4 a0 = *(const float4*)(Ap);                                          \
    float4 a1 = *(const float4*)(Ap + 4);                                      \
    float4 w0 = *(const float4*)(Wp);                                          \
    float4 w1 = *(const float4*)(Wp + 4);                                      \
    PROJ_STS(0)                                                                \
    a0 = *(const float4*)(Ap + PBK);                                           \
    a1 = *(const float4*)(Ap + PBK + 4);                                       \
    w0 = *(const float4*)(Wp + PBK);                                           \
    w1 = *(const float4*)(Wp + PBK + 4);                                       \
    __syncthreads();                                                           \
    int sbuf = 0;                                                              \
    for (int kb = 0; kb < EMBED; kb += PBK) {                                  \
        if (kb + PBK < EMBED) {                                                \
            if (sbuf == 0) { PROJ_STS(1) } else { PROJ_STS(0) }                \
        }                                                                      \
        if (kb + 2*PBK < EMBED) {                                              \
            a0 = *(const float4*)(Ap + kb + 2*PBK);                            \
            a1 = *(const float4*)(Ap + kb + 2*PBK + 4);                        \
            w0 = *(const float4*)(Wp + kb + 2*PBK);                            \
            w1 = *(const float4*)(Wp + kb + 2*PBK + 4);                        \
        }                                                                      \
        _Pragma("unroll")                                                      \
        for (int k = 0; k < PBK; k++) {                                        \
            float4 af0 = *(const float4*)&As[sbuf][k][ty4];                    \
            float4 af1 = *(const float4*)&As[sbuf][k][64 + ty4];               \
            const u64* bp0 = (const u64*)&Bs[sbuf][k][tx4];                    \
            const u64* bp1 = (const u64*)&Bs[sbuf][k][64 + tx4];               \
            u64 b0 = bp0[0], b1 = bp0[1], b2 = bp1[0], b3 = bp1[1];            \
            float ar[8] = {af0.x,af0.y,af0.z,af0.w, af1.x,af1.y,af1.z,af1.w};  \
            _Pragma("unroll")                                                  \
            for (int i = 0; i < 8; i++) {                                      \
                u64 av2 = pk2(ar[i]);                                          \
                fma2(acc2[i][0], av2, b0);                                     \
                fma2(acc2[i][1], av2, b1);                                     \
                fma2(acc2[i][2], av2, b2);                                     \
                fma2(acc2[i][3], av2, b3);                                     \
            }                                                                  \
        }                                                                      \
        __syncthreads();                                                       \
        sbuf ^= 1;                                                             \
    }

// ---------------------------------------------------------------------------
__global__ __launch_bounds__(256, 2) void qkv_proj_kernel(
    const float* __restrict__ X,
    const float* __restrict__ Wq, const float* __restrict__ bq,
    const float* __restrict__ Wk, const float* __restrict__ bk,
    const float* __restrict__ Wv, const float* __restrict__ bv)
{
    const float *W, *bias; float *Out;
    if (blockIdx.z == 0)      { W = Wq; bias = bq; Out = g_q; }
    else if (blockIdx.z == 1) { W = Wk; bias = bk; Out = g_k; }
    else                      { W = Wv; bias = bv; Out = g_v; }

    PROJ_BODY(X, W)

    const int h0 = n0 >> 6;
    const int d  = tx4;
    float4 bb0 = *(const float4*)&bias[n0 + tx4];
    float4 bb1 = *(const float4*)&bias[n0 + 64 + tx4];
#pragma unroll
    for (int i = 0; i < 8; i++) {
        int ro = ((i >> 2) << 6) + ty4 + (i & 3);
        int m  = m0 + ro;
        int b  = m >> 11;
        int n  = m & (SEQ - 1);
        float2 p0 = up2(acc2[i][0]), p1 = up2(acc2[i][1]);
        float2 p2 = up2(acc2[i][2]), p3 = up2(acc2[i][3]);
        float4 o0 = make_float4(p0.x+bb0.x, p0.y+bb0.y, p1.x+bb0.z, p1.y+bb0.w);
        float4 o1 = make_float4(p2.x+bb1.x, p2.y+bb1.y, p3.x+bb1.z, p3.y+bb1.w);
        *(float4*)&Out[((size_t)(b*NHEAD + h0  )*SEQ + n)*HDIM + d] = o0;
        *(float4*)&Out[((size_t)(b*NHEAD + h0+1)*SEQ + n)*HDIM + d] = o1;
    }
}

// ---------------------------------------------------------------------------
__global__ __launch_bounds__(256, 2) void out_proj_kernel(
    const float* __restrict__ Wo, const float* __restrict__ bo,
    float* __restrict__ Outp)
{
    PROJ_BODY(g_h, Wo)

    float4 bb0 = *(const float4*)&bo[n0 + tx4];
    float4 bb1 = *(const float4*)&bo[n0 + 64 + tx4];
#pragma unroll
    for (int i = 0; i < 8; i++) {
        int ro = ((i >> 2) << 6) + ty4 + (i & 3);
        int m  = m0 + ro;
        float2 p0 = up2(acc2[i][0]), p1 = up2(acc2[i][1]);
        float2 p2 = up2(acc2[i][2]), p3 = up2(acc2[i][3]);
        float4 o0 = make_float4(p0.x+bb0.x, p0.y+bb0.y, p1.x+bb0.z, p1.y+bb0.w);
        float4 o1 = make_float4(p2.x+bb1.x, p2.y+bb1.y, p3.x+bb1.z, p3.y+bb1.w);
        *(float4*)&Outp[(size_t)m * EMBED + n0 + tx4]      = o0;
        *(float4*)&Outp[(size_t)m * EMBED + n0 + 64 + tx4] = o1;
    }
}

// ---------------------------------------------------------------------------
// Flash attention: separate Qs/Ks/Vs/Ps buffers, 3 barriers/tile.
// ---------------------------------------------------------------------------
__global__ __launch_bounds__(256, 2) void attn_kernel()
{
    extern __shared__ float sm[];
    float* Qs = sm;                    // [d][q]
    float* Ks = sm + 64*PADP;          // [d][k]
    float* Vs = sm + 2*64*PADP;        // [k][d]
    float* Ps = sm + 3*64*PADP;        // [q][k]
    float* corr_s = sm + 4*64*PADP;
    float* l_s    = corr_s + 64;

    const int tid = threadIdx.x;
    const int bh  = blockIdx.y;
    const int q0  = blockIdx.x << 6;
    const float* Qg = g_q + (size_t)bh * SEQ * HDIM;
    const float* Kg = g_k + (size_t)bh * SEQ * HDIM;
    const float* Vg = g_v + (size_t)bh * SEQ * HDIM;

    const int lr = tid >> 2;
    const int ty = tid >> 4;
    const int tx = tid & 15;
    const int g   = tid >> 6;
    const int t64 = tid & 63;
    const int tr  = t64 >> 3;
    const int tc  = t64 & 7;

    // Q tile transposed -> Qs[d][q]
#pragma unroll
    for (int it = 0; it < 4; it++) {
        int d = it * 16 + ((tid & 3) << 2);
        float4 v = *(const float4*)&Qg[(size_t)(q0 + lr) * HDIM + d];
        Qs[(d+0)*PADP + lr] = v.x;  Qs[(d+1)*PADP + lr] = v.y;
        Qs[(d+2)*PADP + lr] = v.z;  Qs[(d+3)*PADP + lr] = v.w;
    }

    float m_run[4], l_run[4];
    u64 o2[8][4];
#pragma unroll
    for (int i = 0; i < 4; i++) { m_run[i] = -1e30f; l_run[i] = 0.f; }
#pragma unroll
    for (int i = 0; i < 8; i++)
#pragma unroll
        for (int j = 0; j < 4; j++) o2[i][j] = 0ull;

    for (int k0 = 0; k0 < SEQ; k0 += 64) {
        __syncthreads();   // prev PV done (Vs, Ps free); Q staged (iter 0)
        // K transposed + V key-major, loads fused for MLP
#pragma unroll
        for (int it = 0; it < 4; it++) {
            int d = it * 16 + ((tid & 3) << 2);
            float4 kv = *(const float4*)&Kg[(size_t)(k0 + lr) * HDIM + d];
            float4 vv = *(const float4*)&Vg[(size_t)(k0 + lr) * HDIM + d];
            Ks[(d+0)*PADP + lr] = kv.x;  Ks[(d+1)*PADP + lr] = kv.y;
            Ks[(d+2)*PADP + lr] = kv.z;  Ks[(d+3)*PADP + lr] = kv.w;
            *(float4*)&Vs[lr * PADP + d] = vv;
        }
        __syncthreads();

        // S = Q K^T
        u64 s2[4][2] = {{0ull,0ull},{0ull,0ull},{0ull,0ull},{0ull,0ull}};
#pragma unroll 8
        for (int d = 0; d < 64; d++) {
            float4 av = *(const float4*)&Qs[d*PADP + (ty<<2)];
            const u64* bp = (const u64*)&Ks[d*PADP + (tx<<2)];
            u64 b0 = bp[0], b1 = bp[1];
            float ar[4] = {av.x, av.y, av.z, av.w};
#pragma unroll
            for (int i = 0; i < 4; i++) {
                u64 av2 = pk2(ar[i]);
                fma2(s2[i][0], av2, b0);
                fma2(s2[i][1], av2, b1);
            }
        }

        // online softmax
#pragma unroll
        for (int i = 0; i < 4; i++) {
            float2 q0p = up2(s2[i][0]), q1p = up2(s2[i][1]);
            float s[4] = {q0p.x*8.0f, q0p.y*8.0f, q1p.x*8.0f, q1p.y*8.0f};
            float mx = fmaxf(fmaxf(s[0], s[1]), fmaxf(s[2], s[3]));
            mx = fmaxf(mx, __shfl_xor_sync(0xffffffffu, mx, 8, 16));
            mx = fmaxf(mx, __shfl_xor_sync(0xffffffffu, mx, 4, 16));
            mx = fmaxf(mx, __shfl_xor_sync(0xffffffffu, mx, 2, 16));
            mx = fmaxf(mx, __shfl_xor_sync(0xffffffffu, mx, 1, 16));
            float mnew = fmaxf(m_run[i], mx);
            float corr = __expf(m_run[i] - mnew);
            float rs = 0.f;
#pragma unroll
            for (int j = 0; j < 4; j++) {
                float p = __expf(s[j] - mnew);
                s[j] = p; rs += p;
            }
            rs += __shfl_xor_sync(0xffffffffu, rs, 8, 16);
            rs += __shfl_xor_sync(0xffffffffu, rs, 4, 16);
            rs += __shfl_xor_sync(0xffffffffu, rs, 2, 16);
            rs += __shfl_xor_sync(0xffffffffu, rs, 1, 16);
            l_run[i] = l_run[i] * corr + rs;
            m_run[i] = mnew;
            if (tx == 0) corr_s[(ty<<2)+i] = corr;
            *(float4*)&Ps[((ty<<2)+i)*PADP + (tx<<2)] =
                make_float4(s[0], s[1], s[2], s[3]);
        }
        __syncthreads();   // Ps/corr_s ready

        // PV: this group's 16 keys
#pragma unroll
        for (int rr = 0; rr < 8; rr++) {
            u64 c2 = pk2(corr_s[tr*8 + rr]);
            mul2(o2[rr][0], c2); mul2(o2[rr][1], c2);
            mul2(o2[rr][2], c2); mul2(o2[rr][3], c2);
        }

        const int kbase = g << 4;
#pragma unroll
        for (int c4 = 0; c4 < 16; c4 += 4) {
            const int kk = kbase + c4;
            u64 v2[4][4];
#pragma unroll
            for (int u = 0; u < 4; u++) {
                const u64* vp0 = (const u64*)&Vs[(kk+u)*PADP + (tc<<2)];
                const u64* vp1 = (const u64*)&Vs[(kk+u)*PADP + 32 + (tc<<2)];
                v2[u][0] = vp0[0]; v2[u][1] = vp0[1];
                v2[u][2] = vp1[0]; v2[u][3] = vp1[1];
            }
#pragma unroll
            for (int rr = 0; rr < 8; rr++) {
                float4 p = *(const float4*)&Ps[(tr*8+rr)*PADP + kk];
                float pa[4] = {p.x, p.y, p.z, p.w};
#pragma unroll
                for (int u = 0; u < 4; u++) {
                    u64 p2 = pk2(pa[u]);
                    fma2(o2[rr][0], p2, v2[u][0]);
                    fma2(o2[rr][1], p2, v2[u][1]);
                    fma2(o2[rr][2], p2, v2[u][2]);
                    fma2(o2[rr][3], p2, v2[u][3]);
                }
            }
        }
    }

    // unpack
    float o[8][8];
#pragma unroll
    for (int rr = 0; rr < 8; rr++) {
        float2 p0 = up2(o2[rr][0]), p1 = up2(o2[rr][1]);
        float2 p2 = up2(o2[rr][2]), p3 = up2(o2[rr][3]);
        o[rr][0]=p0.x; o[rr][1]=p0.y; o[rr][2]=p1.x; o[rr][3]=p1.y;
        o[rr][4]=p2.x; o[rr][5]=p2.y; o[rr][6]=p3.x; o[rr][7]=p3.y;
    }

    // publish l, merge 4 partial O groups (reuse Qs/Ks/Vs regions)
    if (tx == 0) {
#pragma unroll
        for (int i = 0; i < 4; i++) l_s[(ty<<2)+i] = l_run[i];
    }
    __syncthreads();

    if (g > 0) {
        float* mb = sm + (g-1)*(64*PADP) + t64*PADP;
#pragma unroll
        for (int rr = 0; rr < 8; rr++) {
            *(float4*)&mb[rr*8 + 0] = make_float4(o[rr][0], o[rr][1], o[rr][2], o[rr][3]);
            *(float4*)&mb[rr*8 + 4] = make_float4(o[rr][4], o[rr][5], o[rr][6], o[rr][7]);
        }
    }
    __syncthreads();

    if (g == 0) {
        const int b = bh >> 4;
        const int h = bh & 15;
#pragma unroll
        for (int gg = 0; gg < 3; gg++) {
            const float* mb = sm + gg*(64*PADP) + t64*PADP;
#pragma unroll
            for (int rr = 0; rr < 8; rr++) {
                float4 p0 = *(const float4*)&mb[rr*8 + 0];
                float4 p1 = *(const float4*)&mb[rr*8 + 4];
                o[rr][0] += p0.x; o[rr][1] += p0.y; o[rr][2] += p0.z; o[rr][3] += p0.w;
                o[rr][4] += p1.x; o[rr][5] += p1.y; o[rr][6] += p1.z; o[rr][7] += p1.w;
            }
        }
#pragma unroll
        for (int rr = 0; rr < 8; rr++) {
            int row = tr*8 + rr;
            float inv = 1.0f / l_s[row];
            int q = q0 + row;
            float* dst = &g_h[((size_t)(b*SEQ + q))*EMBED + h*HDIM];
            *(float4*)&dst[(tc<<2)] =
                make_float4(o[rr][0]*inv, o[rr][1]*inv, o[rr][2]*inv, o[rr][3]*inv);
            *(float4*)&dst[32 + (tc<<2)] =
                make_float4(o[rr][4]*inv, o[rr][5]*inv, o[rr][6]*inv, o[rr][7]*inv);
        }
    }
}

// ---------------------------------------------------------------------------
extern "C" void kernel_launch(void* const* d_in, const int* in_sizes, int n_in,
                              void* d_out, int out_size)
{
    const float* x  = (const float*)d_in[0];
    const float* Wq = (const float*)d_in[1];
    const float* bq = (const float*)d_in[2];
    const float* Wk = (const float*)d_in[3];
    const float* bk = (const float*)d_in[4];
    const float* Wv = (const float*)d_in[5];
    const float* bv = (const float*)d_in[6];
    const float* Wo = (const float*)d_in[7];
    const float* bo = (const float*)d_in[8];
    float* out = (float*)d_out;

    cudaFuncSetAttribute(attn_kernel,
                         cudaFuncAttributeMaxDynamicSharedMemorySize, ATTN_SMEM);

    dim3 gproj(EMBED / PBN, MTOT / PBM, 3);
    qkv_proj_kernel<<<gproj, 256>>>(x, Wq, bq, Wk, bk, Wv, bv);

    dim3 gattn(SEQ / 64, BATCH * NHEAD);
    attn_kernel<<<gattn, 256, ATTN_SMEM>>>();

    dim3 gout(EMBED / PBN, MTOT / PBM);
    out_proj_kernel<<<gout, 256>>>(Wo, bo, out);
}

// round 8
// speedup vs baseline: 1.0360x; 1.0360x over previous
#include <cuda_runtime.h>

// Round 8: projections on tensor cores (mma.sync m16n8k8 tf32, 3-term split:
// ahi*bhi + ahi*blo + alo*bhi, residual ~2^-22). Attention reverted to the
// measured-best R6 version (f32x2 SIMT, shared K/V smem buffer).

#define EMBED 1024
#define NHEAD 16
#define HDIM  64
#define BATCH 2
#define SEQ   2048
#define MTOT  (BATCH*SEQ)

#define PBM 128
#define PBN 128
#define PBK 16
#define PADT 136      // (lane&3)*136 + lane/4 -> bank 8*(lane&3)+lane/4: conflict-free

#define PADP 68
#define ATTN_FLOATS (3*64*PADP + 128)
#define ATTN_SMEM   (ATTN_FLOATS*4)

typedef unsigned long long u64;
typedef unsigned int u32;

// ---- f32x2 helpers (attention) ----
__device__ __forceinline__ u64 pk2(float a) {
    u64 r; asm("mov.b64 %0, {%1, %1};" : "=l"(r) : "f"(a)); return r;
}
__device__ __forceinline__ void fma2(u64& d, u64 a, u64 b) {
    asm("fma.rn.f32x2 %0, %1, %2, %0;" : "+l"(d) : "l"(a), "l"(b));
}
__device__ __forceinline__ void mul2(u64& d, u64 a) {
    asm("mul.rn.f32x2 %0, %0, %1;" : "+l"(d) : "l"(a));
}
__device__ __forceinline__ float2 up2(u64 v) {
    float2 r; asm("mov.b64 {%0, %1}, %2;" : "=f"(r.x), "=f"(r.y) : "l"(v)); return r;
}

// ---- tf32 mma helpers (projections) ----
__device__ __forceinline__ void split_tf32(float a, u32& hi, u32& lo) {
    asm("cvt.rna.tf32.f32 %0, %1;" : "=r"(hi) : "f"(a));
    float r = a - __uint_as_float(hi);
    asm("cvt.rna.tf32.f32 %0, %1;" : "=r"(lo) : "f"(r));
}
__device__ __forceinline__ void mma8(float* c, const u32* a, const u32* b) {
    asm("mma.sync.aligned.m16n8k8.row.col.f32.tf32.tf32.f32 "
        "{%0,%1,%2,%3}, {%4,%5,%6,%7}, {%8,%9}, {%0,%1,%2,%3};"
        : "+f"(c[0]), "+f"(c[1]), "+f"(c[2]), "+f"(c[3])
        : "r"(a[0]), "r"(a[1]), "r"(a[2]), "r"(a[3]), "r"(b[0]), "r"(b[1]));
}

__device__ float g_q[BATCH*NHEAD*SEQ*HDIM];
__device__ float g_k[BATCH*NHEAD*SEQ*HDIM];
__device__ float g_v[BATCH*NHEAD*SEQ*HDIM];
__device__ float g_h[MTOT*EMBED];

// ---------------------------------------------------------------------------
// 128x128 tf32-mma GEMM body: C = A @ W^T. Smem k-major: As[k][m], Bs[k][n].
// 8 warps as 2(m) x 4(n); warp tile 64x32 = 4x4 mma tiles (m16n8k8).
// acc c[mi][ni][4]; 3 mma per tile per k8 (split precision).
// ---------------------------------------------------------------------------
#define PROJ_MMA_BODY(APTR, WPTR)                                              \
    __shared__ float As[PBK][PADT];                                            \
    __shared__ float Bs[PBK][PADT];                                            \
    const int tid  = threadIdx.x;                                              \
    const int lane = tid & 31;                                                 \
    const int wid  = tid >> 5;                                                 \
    const int m0 = blockIdx.y * PBM;                                           \
    const int n0 = blockIdx.x * PBN;                                           \
    const int wm = (wid >> 2) << 6;      /* 0 or 64 */                         \
    const int wn = (wid & 3) << 5;       /* 0,32,64,96 */                      \
    const int g4 = lane >> 2;            /* 0..7 */                            \
    const int t4 = lane & 3;             /* 0..3 */                            \
    const int lr  = tid >> 1;                                                  \
    const int lc8 = (tid & 1) << 3;                                            \
    const float* Ap = (APTR) + (size_t)(m0 + lr) * EMBED + lc8;                \
    const float* Wp = (WPTR) + (size_t)(n0 + lr) * EMBED + lc8;                \
    float c[4][4][4];                                                          \
    _Pragma("unroll")                                                          \
    for (int mi = 0; mi < 4; mi++)                                             \
        _Pragma("unroll")                                                      \
        for (int ni = 0; ni < 4; ni++)                                         \
            _Pragma("unroll")                                                  \
            for (int u = 0; u < 4; u++) c[mi][ni][u] = 0.f;                    \
    float4 a0 = *(const float4*)(Ap);                                          \
    float4 a1 = *(const float4*)(Ap + 4);                                      \
    float4 w0 = *(const float4*)(Wp);                                          \
    float4 w1 = *(const float4*)(Wp + 4);                                      \
    for (int kb = 0; kb < EMBED; kb += PBK) {                                  \
        __syncthreads();                                                       \
        As[lc8+0][lr] = a0.x; As[lc8+1][lr] = a0.y;                            \
        As[lc8+2][lr] = a0.z; As[lc8+3][lr] = a0.w;                            \
        As[lc8+4][lr] = a1.x; As[lc8+5][lr] = a1.y;                            \
        As[lc8+6][lr] = a1.z; As[lc8+7][lr] = a1.w;                            \
        Bs[lc8+0][lr] = w0.x; Bs[lc8+1][lr] = w0.y;                            \
        Bs[lc8+2][lr] = w0.z; Bs[lc8+3][lr] = w0.w;                            \
        Bs[lc8+4][lr] = w1.x; Bs[lc8+5][lr] = w1.y;                            \
        Bs[lc8+6][lr] = w1.z; Bs[lc8+7][lr] = w1.w;                            \
        __syncthreads();                                                       \
        if (kb + PBK < EMBED) {                                                \
            a0 = *(const float4*)(Ap + kb + PBK);                              \
            a1 = *(const float4*)(Ap + kb + PBK + 4);                          \
            w0 = *(const float4*)(Wp + kb + PBK);                              \
            w1 = *(const float4*)(Wp + kb + PBK + 4);                          \
        }                                                                      \
        _Pragma("unroll")                                                      \
        for (int k8 = 0; k8 < PBK; k8 += 8) {                                  \
            u32 bhi[4][2], blo[4][2];                                          \
            _Pragma("unroll")                                                  \
            for (int ni = 0; ni < 4; ni++) {                                   \
                float f0 = Bs[k8 + t4    ][wn + ni*8 + g4];                    \
                float f1 = Bs[k8 + t4 + 4][wn + ni*8 + g4];                    \
                split_tf32(f0, bhi[ni][0], blo[ni][0]);                        \
                split_tf32(f1, bhi[ni][1], blo[ni][1]);                        \
            }                                                                  \
            _Pragma("unroll")                                                  \
            for (int mi = 0; mi < 4; mi++) {                                   \
                const int r = wm + mi*16 + g4;                                 \
                float f0 = As[k8 + t4    ][r];                                 \
                float f1 = As[k8 + t4    ][r + 8];                             \
                float f2 = As[k8 + t4 + 4][r];                                 \
                float f3 = As[k8 + t4 + 4][r + 8];                             \
                u32 ahi[4], alo[4];                                            \
                split_tf32(f0, ahi[0], alo[0]);                                \
                split_tf32(f1, ahi[1], alo[1]);                                \
                split_tf32(f2, ahi[2], alo[2]);                                \
                split_tf32(f3, ahi[3], alo[3]);                                \
                _Pragma("unroll")                                              \
                for (int ni = 0; ni < 4; ni++) {                               \
                    mma8(c[mi][ni], ahi, bhi[ni]);                             \
                    mma8(c[mi][ni], ahi, blo[ni]);                             \
                    mma8(c[mi][ni], alo, bhi[ni]);                             \
                }                                                              \
            }                                                                  \
        }                                                                      \
    }

// ---------------------------------------------------------------------------
__global__ __launch_bounds__(256, 2) void qkv_proj_kernel(
    const float* __restrict__ X,
    const float* __restrict__ Wq, const float* __restrict__ bq,
    const float* __restrict__ Wk, const float* __restrict__ bk,
    const float* __restrict__ Wv, const float* __restrict__ bv)
{
    const float *W, *bias; float *Out;
    if (blockIdx.z == 0)      { W = Wq; bias = bq; Out = g_q; }
    else if (blockIdx.z == 1) { W = Wk; bias = bk; Out = g_k; }
    else                      { W = Wv; bias = bv; Out = g_v; }

    PROJ_MMA_BODY(X, W)

#pragma unroll
    for (int mi = 0; mi < 4; mi++) {
#pragma unroll
        for (int ni = 0; ni < 4; ni++) {
            const int col = n0 + wn + ni*8 + 2*t4;
            const int h   = col >> 6;
            const int d   = col & 63;
            float2 bb = *(const float2*)&bias[col];
#pragma unroll
            for (int half = 0; half < 2; half++) {
                int row = m0 + wm + mi*16 + g4 + half*8;
                int b   = row >> 11;
                int n   = row & (SEQ - 1);
                float2 o = make_float2(c[mi][ni][2*half+0] + bb.x,
                                       c[mi][ni][2*half+1] + bb.y);
                *(float2*)&Out[((size_t)(b*NHEAD + h)*SEQ + n)*HDIM + d] = o;
            }
        }
    }
}

// ---------------------------------------------------------------------------
__global__ __launch_bounds__(256, 2) void out_proj_kernel(
    const float* __restrict__ Wo, const float* __restrict__ bo,
    float* __restrict__ Outp)
{
    PROJ_MMA_BODY(g_h, Wo)

#pragma unroll
    for (int mi = 0; mi < 4; mi++) {
#pragma unroll
        for (int ni = 0; ni < 4; ni++) {
            const int col = n0 + wn + ni*8 + 2*t4;
            float2 bb = *(const float2*)&bo[col];
#pragma unroll
            for (int half = 0; half < 2; half++) {
                int row = m0 + wm + mi*16 + g4 + half*8;
                float2 o = make_float2(c[mi][ni][2*half+0] + bb.x,
                                       c[mi][ni][2*half+1] + bb.y);
                *(float2*)&Outp[(size_t)row * EMBED + col] = o;
            }
        }
    }
}

// ---------------------------------------------------------------------------
// Flash attention (R6 measured-best): f32x2 inner loops, shared K/V buffer.
// ---------------------------------------------------------------------------
__global__ __launch_bounds__(256, 2) void attn_kernel()
{
    extern __shared__ float sm[];
    float* Qs  = sm;
    float* KVs = sm + 64*PADP;
    float* Ps  = sm + 2*64*PADP;
    float* corr_s = sm + 3*64*PADP;
    float* l_s    = corr_s + 64;

    const int tid = threadIdx.x;
    const int bh  = blockIdx.y;
    const int q0  = blockIdx.x << 6;
    const float* Qg = g_q + (size_t)bh * SEQ * HDIM;
    const float* Kg = g_k + (size_t)bh * SEQ * HDIM;
    const float* Vg = g_v + (size_t)bh * SEQ * HDIM;

    const int lr = tid >> 2;
    const int ty = tid >> 4;
    const int tx = tid & 15;
    const int g   = tid >> 6;
    const int t64 = tid & 63;
    const int tr  = t64 >> 3;
    const int tc  = t64 & 7;

#pragma unroll
    for (int it = 0; it < 4; it++) {
        int d = it * 16 + ((tid & 3) << 2);
        float4 v = *(const float4*)&Qg[(size_t)(q0 + lr) * HDIM + d];
        Qs[(d+0)*PADP + lr] = v.x;  Qs[(d+1)*PADP + lr] = v.y;
        Qs[(d+2)*PADP + lr] = v.z;  Qs[(d+3)*PADP + lr] = v.w;
    }

    float m_run[4], l_run[4];
    u64 o2[8][4];
#pragma unroll
    for (int i = 0; i < 4; i++) { m_run[i] = -1e30f; l_run[i] = 0.f; }
#pragma unroll
    for (int i = 0; i < 8; i++)
#pragma unroll
        for (int j = 0; j < 4; j++) o2[i][j] = 0ull;

    for (int k0 = 0; k0 < SEQ; k0 += 64) {
        __syncthreads();
#pragma unroll
        for (int it = 0; it < 4; it++) {
            int d = it * 16 + ((tid & 3) << 2);
            float4 kv = *(const float4*)&Kg[(size_t)(k0 + lr) * HDIM + d];
            KVs[(d+0)*PADP + lr] = kv.x;  KVs[(d+1)*PADP + lr] = kv.y;
            KVs[(d+2)*PADP + lr] = kv.z;  KVs[(d+3)*PADP + lr] = kv.w;
        }
        __syncthreads();

        u64 s2[4][2] = {{0ull,0ull},{0ull,0ull},{0ull,0ull},{0ull,0ull}};
#pragma unroll 8
        for (int d = 0; d < 64; d++) {
            float4 av = *(const float4*)&Qs[d*PADP + (ty<<2)];
            const u64* bp = (const u64*)&KVs[d*PADP + (tx<<2)];
            u64 b0 = bp[0], b1 = bp[1];
            float ar[4] = {av.x, av.y, av.z, av.w};
#pragma unroll
            for (int i = 0; i < 4; i++) {
                u64 av2 = pk2(ar[i]);
                fma2(s2[i][0], av2, b0);
                fma2(s2[i][1], av2, b1);
            }
        }

#pragma unroll
        for (int i = 0; i < 4; i++) {
            float2 q0p = up2(s2[i][0]), q1p = up2(s2[i][1]);
            float s[4] = {q0p.x*8.0f, q0p.y*8.0f, q1p.x*8.0f, q1p.y*8.0f};
            float mx = fmaxf(fmaxf(s[0], s[1]), fmaxf(s[2], s[3]));
            mx = fmaxf(mx, __shfl_xor_sync(0xffffffffu, mx, 8, 16));
            mx = fmaxf(mx, __shfl_xor_sync(0xffffffffu, mx, 4, 16));
            mx = fmaxf(mx, __shfl_xor_sync(0xffffffffu, mx, 2, 16));
            mx = fmaxf(mx, __shfl_xor_sync(0xffffffffu, mx, 1, 16));
            float mnew = fmaxf(m_run[i], mx);
            float corr = __expf(m_run[i] - mnew);
            float rs = 0.f;
#pragma unroll
            for (int j = 0; j < 4; j++) {
                float p = __expf(s[j] - mnew);
                s[j] = p; rs += p;
            }
            rs += __shfl_xor_sync(0xffffffffu, rs, 8, 16);
            rs += __shfl_xor_sync(0xffffffffu, rs, 4, 16);
            rs += __shfl_xor_sync(0xffffffffu, rs, 2, 16);
            rs += __shfl_xor_sync(0xffffffffu, rs, 1, 16);
            l_run[i] = l_run[i] * corr + rs;
            m_run[i] = mnew;
            if (tx == 0) corr_s[(ty<<2)+i] = corr;
            *(float4*)&Ps[((ty<<2)+i)*PADP + (tx<<2)] =
                make_float4(s[0], s[1], s[2], s[3]);
        }
        __syncthreads();

#pragma unroll
        for (int it = 0; it < 4; it++) {
            int d = it * 16 + ((tid & 3) << 2);
            float4 vv = *(const float4*)&Vg[(size_t)(k0 + lr) * HDIM + d];
            *(float4*)&KVs[lr * PADP + d] = vv;
        }
        __syncthreads();

#pragma unroll
        for (int rr = 0; rr < 8; rr++) {
            u64 c2 = pk2(corr_s[tr*8 + rr]);
            mul2(o2[rr][0], c2); mul2(o2[rr][1], c2);
            mul2(o2[rr][2], c2); mul2(o2[rr][3], c2);
        }

        const int kbase = g << 4;
#pragma unroll
        for (int c4 = 0; c4 < 16; c4 += 4) {
            const int kk = kbase + c4;
            u64 v2[4][4];
#pragma unroll
            for (int u = 0; u < 4; u++) {
                const u64* vp0 = (const u64*)&KVs[(kk+u)*PADP + (tc<<2)];
                const u64* vp1 = (const u64*)&KVs[(kk+u)*PADP + 32 + (tc<<2)];
                v2[u][0] = vp0[0]; v2[u][1] = vp0[1];
                v2[u][2] = vp1[0]; v2[u][3] = vp1[1];
            }
#pragma unroll
            for (int rr = 0; rr < 8; rr++) {
                float4 p = *(const float4*)&Ps[(tr*8+rr)*PADP + kk];
                float pa[4] = {p.x, p.y, p.z, p.w};
#pragma unroll
                for (int u = 0; u < 4; u++) {
                    u64 p2 = pk2(pa[u]);
                    fma2(o2[rr][0], p2, v2[u][0]);
                    fma2(o2[rr][1], p2, v2[u][1]);
                    fma2(o2[rr][2], p2, v2[u][2]);
                    fma2(o2[rr][3], p2, v2[u][3]);
                }
            }
        }
    }

    float o[8][8];
#pragma unroll
    for (int rr = 0; rr < 8; rr++) {
        float2 p0 = up2(o2[rr][0]), p1 = up2(o2[rr][1]);
        float2 p2 = up2(o2[rr][2]), p3 = up2(o2[rr][3]);
        o[rr][0]=p0.x; o[rr][1]=p0.y; o[rr][2]=p1.x; o[rr][3]=p1.y;
        o[rr][4]=p2.x; o[rr][5]=p2.y; o[rr][6]=p3.x; o[rr][7]=p3.y;
    }

    if (tx == 0) {
#pragma unroll
        for (int i = 0; i < 4; i++) l_s[(ty<<2)+i] = l_run[i];
    }
    __syncthreads();

    if (g > 0) {
        float* mb = sm + (g-1)*(64*PADP) + t64*PADP;
#pragma unroll
        for (int rr = 0; rr < 8; rr++) {
            *(float4*)&mb[rr*8 + 0] = make_float4(o[rr][0], o[rr][1], o[rr][2], o[rr][3]);
            *(float4*)&mb[rr*8 + 4] = make_float4(o[rr][4], o[rr][5], o[rr][6], o[rr][7]);
        }
    }
    __syncthreads();

    if (g == 0) {
        const int b = bh >> 4;
        const int h = bh & 15;
#pragma unroll
        for (int gg = 0; gg < 3; gg++) {
            const float* mb = sm + gg*(64*PADP) + t64*PADP;
#pragma unroll
            for (int rr = 0; rr < 8; rr++) {
                float4 p0 = *(const float4*)&mb[rr*8 + 0];
                float4 p1 = *(const float4*)&mb[rr*8 + 4];
                o[rr][0] += p0.x; o[rr][1] += p0.y; o[rr][2] += p0.z; o[rr][3] += p0.w;
                o[rr][4] += p1.x; o[rr][5] += p1.y; o[rr][6] += p1.z; o[rr][7] += p1.w;
            }
        }
#pragma unroll
        for (int rr = 0; rr < 8; rr++) {
            int row = tr*8 + rr;
            float inv = 1.0f / l_s[row];
            int q = q0 + row;
            float* dst = &g_h[((size_t)(b*SEQ + q))*EMBED + h*HDIM];
            *(float4*)&dst[(tc<<2)] =
                make_float4(o[rr][0]*inv, o[rr][1]*inv, o[rr][2]*inv, o[rr][3]*inv);
            *(float4*)&dst[32 + (tc<<2)] =
                make_float4(o[rr][4]*inv, o[rr][5]*inv, o[rr][6]*inv, o[rr][7]*inv);
        }
    }
}

// ---------------------------------------------------------------------------
extern "C" void kernel_launch(void* const* d_in, const int* in_sizes, int n_in,
                              void* d_out, int out_size)
{
    const float* x  = (const float*)d_in[0];
    const float* Wq = (const float*)d_in[1];
    const float* bq = (const float*)d_in[2];
    const float* Wk = (const float*)d_in[3];
    const float* bk = (const float*)d_in[4];
    const float* Wv = (const float*)d_in[5];
    const float* bv = (const float*)d_in[6];
    const float* Wo = (const float*)d_in[7];
    const float* bo = (const float*)d_in[8];
    float* out = (float*)d_out;

    cudaFuncSetAttribute(attn_kernel,
                         cudaFuncAttributeMaxDynamicSharedMemorySize, ATTN_SMEM);

    dim3 gproj(EMBED / PBN, MTOT / PBM, 3);
    qkv_proj_kernel<<<gproj, 256>>>(x, Wq, bq, Wk, bk, Wv, bv);

    dim3 gattn(SEQ / 64, BATCH * NHEAD);
    attn_kernel<<<gattn, 256, ATTN_SMEM>>>();

    dim3 gout(EMBED / PBN, MTOT / PBM);
    out_proj_kernel<<<gout, 256>>>(Wo, bo, out);
}